// round 3
// baseline (speedup 1.0000x reference)
#include <cuda_runtime.h>
#include <math_constants.h>

#define NN   50000
#define EE   1600000
#define D    64
#define DE   16
#define ATT_SLOPE 0.2f
#define ACT_SLOPE 0.01f

typedef unsigned long long u64;
union F2U { u64 u; float2 f; };

__device__ __forceinline__ u64 fma2(u64 a, u64 b, u64 c) {
    u64 d; asm("fma.rn.f32x2 %0, %1, %2, %3;" : "=l"(d) : "l"(a), "l"(b), "l"(c));
    return d;
}
__device__ __forceinline__ u64 pack2(float x, float y) {
    F2U t; t.f = make_float2(x, y); return t.u;
}

// ---------------- scratch (device globals; no allocation allowed) -----------
__device__ float2 g_h [NN * 32];    // transformed features, dim pairs (2l,2l+1)
__device__ float2 g_c1[NN * 32];    // layer-1 output
__device__ float  g_hs[NN];
__device__ float  g_hd[NN];
__device__ float4 g_ea[EE * 4];     // edge_attr in CSR order (16 floats/edge)
__device__ float  g_dot1[EE];       // edge_attr @ (We1@ae1), CSR order
__device__ float  g_dot2[EE];       // edge_attr @ (We2@ae2), CSR order
__device__ int    g_srcc[EE];       // CSR-ordered src node
__device__ int    g_deg[NN];
__device__ int    g_rowptr[NN + 1];
__device__ int    g_cursor[NN];
__device__ int    g_bsum[64];
__device__ float  g_wea1[DE], g_wea2[DE];

// ---------------- tiny prep: wea = We @ ae for both layers -------------------
__global__ void k_prep(const float* __restrict__ We1, const float* __restrict__ ae1,
                       const float* __restrict__ We2, const float* __restrict__ ae2) {
    int t = threadIdx.x;
    if (t < DE) {
        float a = 0.f;
        #pragma unroll
        for (int d = 0; d < D; d++) a = fmaf(We1[t * D + d], ae1[d], a);
        g_wea1[t] = a;
    } else {
        int j = t - DE;
        float a = 0.f;
        #pragma unroll
        for (int d = 0; d < D; d++) a = fmaf(We2[j * D + d], ae2[d], a);
        g_wea2[j] = a;
    }
}

// ---------------- CSR construction ------------------------------------------
__global__ void k_zero_deg() {
    int i = blockIdx.x * blockDim.x + threadIdx.x;
    if (i < NN) g_deg[i] = 0;
}

__global__ void k_hist(const int* __restrict__ dst) {
    int i = blockIdx.x * blockDim.x + threadIdx.x;
    if (i < EE / 4) {
        int4 v = ((const int4*)dst)[i];
        atomicAdd(&g_deg[v.x], 1);
        atomicAdd(&g_deg[v.y], 1);
        atomicAdd(&g_deg[v.z], 1);
        atomicAdd(&g_deg[v.w], 1);
    }
}

__global__ void k_scan1() {
    __shared__ int wsum[32];
    int tid = threadIdx.x, lane = tid & 31, wid = tid >> 5;
    int i = blockIdx.x * 1024 + tid;
    int v = (i < NN) ? g_deg[i] : 0;
    int x = v;
    #pragma unroll
    for (int o = 1; o < 32; o <<= 1) {
        int t = __shfl_up_sync(0xffffffffu, x, o);
        if (lane >= o) x += t;
    }
    if (lane == 31) wsum[wid] = x;
    __syncthreads();
    if (wid == 0) {
        int w = wsum[lane];
        #pragma unroll
        for (int o = 1; o < 32; o <<= 1) {
            int t = __shfl_up_sync(0xffffffffu, w, o);
            if (lane >= o) w += t;
        }
        wsum[lane] = w;
    }
    __syncthreads();
    int off = wid ? wsum[wid - 1] : 0;
    if (i < NN) g_rowptr[i] = x - v + off;
    if (tid == 1023) g_bsum[blockIdx.x] = x + off;
}

__global__ void k_scan2() {
    int i = blockIdx.x * blockDim.x + threadIdx.x;
    if (i == 0) g_rowptr[NN] = EE;
    if (i < NN) {
        int b = i >> 10;
        int off = 0;
        for (int j = 0; j < b; j++) off += g_bsum[j];
        int r = g_rowptr[i] + off;
        g_rowptr[i] = r;
        g_cursor[i] = r;
    }
}

// scatter: build CSR src list, reorder edge_attr, precompute attention dots
__global__ void k_scatter(const int* __restrict__ src, const int* __restrict__ dst,
                          const float* __restrict__ eattr) {
    __shared__ float sw1[DE], sw2[DE];
    if (threadIdx.x < DE) sw1[threadIdx.x] = g_wea1[threadIdx.x];
    else if (threadIdx.x < 2 * DE) sw2[threadIdx.x - DE] = g_wea2[threadIdx.x - DE];
    __syncthreads();
    int i = blockIdx.x * blockDim.x + threadIdx.x;
    if (i < EE / 4) {
        int4 dv = ((const int4*)dst)[i];
        int4 sv = ((const int4*)src)[i];
        const int* dp = &dv.x;
        const int* sp = &sv.x;
        #pragma unroll
        for (int r = 0; r < 4; r++) {
            int e = 4 * i + r;
            const float4* ea4 = (const float4*)(eattr + (size_t)e * DE);
            float4 A = ea4[0], B = ea4[1], C = ea4[2], Dd = ea4[3];
            const float* ev = &A.x;   // A,B,C,Dd contiguous on stack
            float d1 = 0.f, d2 = 0.f;
            #pragma unroll
            for (int k = 0; k < 4; k++) { d1 = fmaf((&A.x)[k],  sw1[k],      d1); d2 = fmaf((&A.x)[k],  sw2[k],      d2); }
            #pragma unroll
            for (int k = 0; k < 4; k++) { d1 = fmaf((&B.x)[k],  sw1[k + 4],  d1); d2 = fmaf((&B.x)[k],  sw2[k + 4],  d2); }
            #pragma unroll
            for (int k = 0; k < 4; k++) { d1 = fmaf((&C.x)[k],  sw1[k + 8],  d1); d2 = fmaf((&C.x)[k],  sw2[k + 8],  d2); }
            #pragma unroll
            for (int k = 0; k < 4; k++) { d1 = fmaf((&Dd.x)[k], sw1[k + 12], d1); d2 = fmaf((&Dd.x)[k], sw2[k + 12], d2); }
            int p = atomicAdd(&g_cursor[dp[r]], 1);
            g_srcc[p] = sp[r];
            g_dot1[p] = d1;
            g_dot2[p] = d2;
            float4* o = &g_ea[(size_t)p * 4];
            o[0] = A; o[1] = B; o[2] = C; o[3] = Dd;
            (void)ev;
        }
    }
}

// ---------------- feature transform: h = x@W, hs = h.a_s, hd = h.a_d --------
__global__ void __launch_bounds__(256) k_feat(const float* __restrict__ xin,
                                              const float* __restrict__ W,
                                              const float* __restrict__ a_s,
                                              const float* __restrict__ a_d,
                                              int use_c1) {
    __shared__ u64 sW2[D * 32];
    __shared__ float sx[8][4][D];
    __shared__ u64 sas2[32], sad2[32];
    const float* __restrict__ x = use_c1 ? (const float*)g_c1 : xin;
    int tid = threadIdx.x;
    for (int i = tid; i < D * 32; i += 256) sW2[i] = ((const u64*)W)[i];
    if (tid < 32) { sas2[tid] = ((const u64*)a_s)[tid]; sad2[tid] = ((const u64*)a_d)[tid]; }
    __syncthreads();
    int warp = tid >> 5, lane = tid & 31;
    F2U asv; asv.u = sas2[lane];
    F2U adv; adv.u = sad2[lane];
    int gw = blockIdx.x * 8 + warp;
    int nw = gridDim.x * 8;
    for (int r0 = gw * 4; r0 < NN; r0 += nw * 4) {
        #pragma unroll
        for (int r = 0; r < 4; r++) {
            int row = r0 + r;
            sx[warp][r][lane]      = x[row * D + lane];
            sx[warp][r][lane + 32] = x[row * D + lane + 32];
        }
        __syncwarp();
        F2U acc[4];
        #pragma unroll
        for (int r = 0; r < 4; r++) acc[r].u = 0ull;
        #pragma unroll
        for (int k = 0; k < D; k++) {
            u64 wp = sW2[k * 32 + lane];
            #pragma unroll
            for (int r = 0; r < 4; r++) {
                float xv = sx[warp][r][k];
                acc[r].u = fma2(pack2(xv, xv), wp, acc[r].u);
            }
        }
        #pragma unroll
        for (int r = 0; r < 4; r++) {
            int row = r0 + r;
            g_h[row * 32 + lane] = acc[r].f;
            float ps = acc[r].f.x * asv.f.x + acc[r].f.y * asv.f.y;
            float pd = acc[r].f.x * adv.f.x + acc[r].f.y * adv.f.y;
            #pragma unroll
            for (int o = 16; o; o >>= 1) {
                ps += __shfl_xor_sync(0xffffffffu, ps, o);
                pd += __shfl_xor_sync(0xffffffffu, pd, o);
            }
            if (lane == 0) { g_hs[row] = ps; g_hd[row] = pd; }
        }
        __syncwarp();
    }
}

// ---------------- fused GAT: single-sweep online softmax + max aggregation --
// warp per dst node; lane owns dim pair (2l, 2l+1); We resident in registers
__global__ void __launch_bounds__(256) k_gat(const float* __restrict__ We,
                                             const float* __restrict__ bias,
                                             float* __restrict__ dout,
                                             int layer2) {
    __shared__ u64 sb2[32];
    float* __restrict__ out = layer2 ? dout : (float*)g_c1;
    const float* __restrict__ dot = layer2 ? g_dot2 : g_dot1;
    int tid = threadIdx.x, lane = tid & 31, warp = tid >> 5;
    if (tid < 32) sb2[tid] = ((const u64*)bias)[tid];
    __syncthreads();

    // register-resident We k-pairs for this lane's two dims
    int d0 = 2 * lane, d1 = d0 + 1;
    u64 wd0[8], wd1[8];
    #pragma unroll
    for (int j = 0; j < 8; j++) {
        wd0[j] = pack2(We[(2 * j) * D + d0], We[(2 * j + 1) * D + d0]);
        wd1[j] = pack2(We[(2 * j) * D + d1], We[(2 * j + 1) * D + d1]);
    }
    F2U bv; bv.u = sb2[lane];

    int gw = blockIdx.x * 8 + warp;
    int nw = gridDim.x * 8;

    for (int n = gw; n < NN; n += nw) {
        int beg = g_rowptr[n], end = g_rowptr[n + 1];
        float o0, o1;
        if (beg == end) {
            o0 = 0.f; o1 = 0.f;
        } else {
            float hdn = g_hd[n];
            float m = -CUDART_INF_F, s = 0.f;
            float a0 = -CUDART_INF_F, a1 = -CUDART_INF_F;
            for (int base = beg; base < end; base += 32) {
                int idx = base + lane;
                bool valid = idx < end;
                int sr  = valid ? g_srcc[idx] : 0;
                float l;
                if (valid) {
                    l = g_hs[sr] + hdn + dot[idx];
                    l = fmaxf(l, ATT_SLOPE * l);         // leaky_relu(l, 0.2)
                } else {
                    l = -CUDART_INF_F;
                }
                float cm = l;
                #pragma unroll
                for (int o = 16; o; o >>= 1)
                    cm = fmaxf(cm, __shfl_xor_sync(0xffffffffu, cm, o));
                float nmx;
                if (base == beg) {
                    nmx = cm;
                } else {
                    nmx = fmaxf(m, cm);
                    float f = __expf(m - nmx);           // in (0,1]
                    s *= f; a0 *= f; a1 *= f;
                }
                m = nmx;
                float p = valid ? __expf(l - nmx) : 0.f; // arg <= 0
                float ps = p;
                #pragma unroll
                for (int o = 16; o; o >>= 1)
                    ps += __shfl_xor_sync(0xffffffffu, ps, o);
                s += ps;

                int cnt = min(32, end - base);
                for (int j = 0; j < cnt; j++) {
                    float pj  = __shfl_sync(0xffffffffu, p,  j);
                    int   srj = __shfl_sync(0xffffffffu, sr, j);
                    const float4* ea4 = &g_ea[(size_t)(base + j) * 4];
                    float4 A = ea4[0], B = ea4[1], C = ea4[2], Dd = ea4[3];
                    F2U hu; hu.f = g_h[srj * 32 + lane];
                    u64 p0 = pack2(A.x,  A.y);
                    u64 p1 = pack2(A.z,  A.w);
                    u64 p2 = pack2(B.x,  B.y);
                    u64 p3 = pack2(B.z,  B.w);
                    u64 p4 = pack2(C.x,  C.y);
                    u64 p5 = pack2(C.z,  C.w);
                    u64 p6 = pack2(Dd.x, Dd.y);
                    u64 p7 = pack2(Dd.z, Dd.w);
                    u64 e0 = 0ull, e1 = 0ull;
                    e0 = fma2(p0, wd0[0], e0);  e1 = fma2(p0, wd1[0], e1);
                    e0 = fma2(p1, wd0[1], e0);  e1 = fma2(p1, wd1[1], e1);
                    e0 = fma2(p2, wd0[2], e0);  e1 = fma2(p2, wd1[2], e1);
                    e0 = fma2(p3, wd0[3], e0);  e1 = fma2(p3, wd1[3], e1);
                    e0 = fma2(p4, wd0[4], e0);  e1 = fma2(p4, wd1[4], e1);
                    e0 = fma2(p5, wd0[5], e0);  e1 = fma2(p5, wd1[5], e1);
                    e0 = fma2(p6, wd0[6], e0);  e1 = fma2(p6, wd1[6], e1);
                    e0 = fma2(p7, wd0[7], e0);  e1 = fma2(p7, wd1[7], e1);
                    F2U E0; E0.u = e0;
                    F2U E1; E1.u = e1;
                    float v0 = hu.f.x + (E0.f.x + E0.f.y);
                    float v1 = hu.f.y + (E1.f.x + E1.f.y);
                    a0 = fmaxf(a0, pj * v0);
                    a1 = fmaxf(a1, pj * v1);
                }
            }
            float inv = 1.0f / s;                        // s >= 1 always
            o0 = a0 * inv;
            o1 = a1 * inv;
        }
        o0 += bv.f.x;
        o1 += bv.f.y;
        o0 = fmaxf(o0, ACT_SLOPE * o0);                  // leaky_relu(., 0.01)
        o1 = fmaxf(o1, ACT_SLOPE * o1);
        ((float2*)out)[n * 32 + lane] = make_float2(o0, o1);
    }
}

// ---------------- launch -----------------------------------------------------
extern "C" void kernel_launch(void* const* d_in, const int* in_sizes, int n_in,
                              void* d_out, int out_size) {
    const float* X     = (const float*)d_in[0];
    const int*   ei    = (const int*)  d_in[1];
    const float* eattr = (const float*)d_in[2];
    const float* W1  = (const float*)d_in[3];
    const float* We1 = (const float*)d_in[4];
    const float* as1 = (const float*)d_in[5];
    const float* ad1 = (const float*)d_in[6];
    const float* ae1 = (const float*)d_in[7];
    const float* b1  = (const float*)d_in[8];
    const float* W2  = (const float*)d_in[9];
    const float* We2 = (const float*)d_in[10];
    const float* as2 = (const float*)d_in[11];
    const float* ad2 = (const float*)d_in[12];
    const float* ae2 = (const float*)d_in[13];
    const float* b2  = (const float*)d_in[14];

    const int* srcp = ei;
    const int* dstp = ei + EE;
    float* out = (float*)d_out;

    const int E4B = (EE / 4 + 255) / 256;        // 1563
    const int NB  = (NN + 255) / 256;            // 196
    const int SB  = (NN + 1023) / 1024;          // 49
    const int FB  = 296;
    const int GB  = 444;

    // CSR build + edge preprocessing (once per launch, shared by both layers)
    k_prep<<<1, 32>>>(We1, ae1, We2, ae2);
    k_zero_deg<<<NB, 256>>>();
    k_hist<<<E4B, 256>>>(dstp);
    k_scan1<<<SB, 1024>>>();
    k_scan2<<<NB, 256>>>();
    k_scatter<<<E4B, 256>>>(srcp, dstp, eattr);

    // layer 1
    k_feat<<<FB, 256>>>(X, W1, as1, ad1, /*use_c1=*/0);
    k_gat <<<GB, 256>>>(We1, b1, out, /*layer2=*/0);

    // layer 2
    k_feat<<<FB, 256>>>(nullptr, W2, as2, ad2, /*use_c1=*/1);
    k_gat <<<GB, 256>>>(We2, b2, out, /*layer2=*/1);
}

// round 4
// speedup vs baseline: 1.2874x; 1.2874x over previous
#include <cuda_runtime.h>
#include <math_constants.h>

#define NN   50000
#define EE   1600000
#define D    64
#define DE   16
#define ATT_SLOPE 0.2f
#define ACT_SLOPE 0.01f

typedef unsigned long long u64;
union F2U { u64 u; float2 f; };

__device__ __forceinline__ u64 fma2(u64 a, u64 b, u64 c) {
    u64 d; asm("fma.rn.f32x2 %0, %1, %2, %3;" : "=l"(d) : "l"(a), "l"(b), "l"(c));
    return d;
}
__device__ __forceinline__ u64 pack2(float x, float y) {
    F2U t; t.f = make_float2(x, y); return t.u;
}

// ---------------- scratch (device globals; no allocation allowed) -----------
__device__ float2 g_h [NN * 32];    // transformed features, dim pairs (2l,2l+1)
__device__ float2 g_c1[NN * 32];    // layer-1 output
__device__ float  g_hs[NN];
__device__ float  g_hd[NN];
__device__ float4 g_ea[EE * 4];     // edge_attr in CSR order (16 floats/edge)
__device__ float  g_dot1[EE];       // edge_attr @ (We1@ae1), CSR order
__device__ float  g_dot2[EE];       // edge_attr @ (We2@ae2), CSR order
__device__ float  g_l [EE];         // per-edge p (CSR order)
__device__ int    g_srcc[EE];       // CSR-ordered src node
__device__ int    g_deg[NN];
__device__ int    g_rowptr[NN + 1];
__device__ int    g_cursor[NN];
__device__ int    g_bsum[64];
__device__ float  g_wea1[DE], g_wea2[DE];

// ---------------- tiny prep: wea = We @ ae for both layers -------------------
__global__ void k_prep(const float* __restrict__ We1, const float* __restrict__ ae1,
                       const float* __restrict__ We2, const float* __restrict__ ae2) {
    int t = threadIdx.x;
    if (t < DE) {
        float a = 0.f;
        #pragma unroll
        for (int d = 0; d < D; d++) a = fmaf(We1[t * D + d], ae1[d], a);
        g_wea1[t] = a;
    } else {
        int j = t - DE;
        float a = 0.f;
        #pragma unroll
        for (int d = 0; d < D; d++) a = fmaf(We2[j * D + d], ae2[d], a);
        g_wea2[j] = a;
    }
}

// ---------------- CSR construction ------------------------------------------
__global__ void k_zero_deg() {
    int i = blockIdx.x * blockDim.x + threadIdx.x;
    if (i < NN) g_deg[i] = 0;
}

__global__ void k_hist(const int* __restrict__ dst) {
    int i = blockIdx.x * blockDim.x + threadIdx.x;
    if (i < EE / 4) {
        int4 v = ((const int4*)dst)[i];
        atomicAdd(&g_deg[v.x], 1);
        atomicAdd(&g_deg[v.y], 1);
        atomicAdd(&g_deg[v.z], 1);
        atomicAdd(&g_deg[v.w], 1);
    }
}

__global__ void k_scan1() {
    __shared__ int wsum[32];
    int tid = threadIdx.x, lane = tid & 31, wid = tid >> 5;
    int i = blockIdx.x * 1024 + tid;
    int v = (i < NN) ? g_deg[i] : 0;
    int x = v;
    #pragma unroll
    for (int o = 1; o < 32; o <<= 1) {
        int t = __shfl_up_sync(0xffffffffu, x, o);
        if (lane >= o) x += t;
    }
    if (lane == 31) wsum[wid] = x;
    __syncthreads();
    if (wid == 0) {
        int w = wsum[lane];
        #pragma unroll
        for (int o = 1; o < 32; o <<= 1) {
            int t = __shfl_up_sync(0xffffffffu, w, o);
            if (lane >= o) w += t;
        }
        wsum[lane] = w;
    }
    __syncthreads();
    int off = wid ? wsum[wid - 1] : 0;
    if (i < NN) g_rowptr[i] = x - v + off;
    if (tid == 1023) g_bsum[blockIdx.x] = x + off;
}

__global__ void k_scan2() {
    int i = blockIdx.x * blockDim.x + threadIdx.x;
    if (i == 0) g_rowptr[NN] = EE;
    if (i < NN) {
        int b = i >> 10;
        int off = 0;
        for (int j = 0; j < b; j++) off += g_bsum[j];
        int r = g_rowptr[i] + off;
        g_rowptr[i] = r;
        g_cursor[i] = r;
    }
}

// scatter: CSR src list, reorder edge_attr, precompute attention dots
__global__ void k_scatter(const int* __restrict__ src, const int* __restrict__ dst,
                          const float* __restrict__ eattr) {
    __shared__ float sw1[DE], sw2[DE];
    if (threadIdx.x < DE) sw1[threadIdx.x] = g_wea1[threadIdx.x];
    else if (threadIdx.x < 2 * DE) sw2[threadIdx.x - DE] = g_wea2[threadIdx.x - DE];
    __syncthreads();
    int i = blockIdx.x * blockDim.x + threadIdx.x;
    if (i < EE / 4) {
        int4 dv = ((const int4*)dst)[i];
        int4 sv = ((const int4*)src)[i];
        const int* dp = &dv.x;
        const int* sp = &sv.x;
        #pragma unroll
        for (int r = 0; r < 4; r++) {
            int e = 4 * i + r;
            const float4* ea4 = (const float4*)(eattr + (size_t)e * DE);
            float4 A = ea4[0], B = ea4[1], C = ea4[2], Dd = ea4[3];
            float d1 = 0.f, d2 = 0.f;
            #pragma unroll
            for (int k = 0; k < 4; k++) { d1 = fmaf((&A.x)[k],  sw1[k],      d1); d2 = fmaf((&A.x)[k],  sw2[k],      d2); }
            #pragma unroll
            for (int k = 0; k < 4; k++) { d1 = fmaf((&B.x)[k],  sw1[k + 4],  d1); d2 = fmaf((&B.x)[k],  sw2[k + 4],  d2); }
            #pragma unroll
            for (int k = 0; k < 4; k++) { d1 = fmaf((&C.x)[k],  sw1[k + 8],  d1); d2 = fmaf((&C.x)[k],  sw2[k + 8],  d2); }
            #pragma unroll
            for (int k = 0; k < 4; k++) { d1 = fmaf((&Dd.x)[k], sw1[k + 12], d1); d2 = fmaf((&Dd.x)[k], sw2[k + 12], d2); }
            int p = atomicAdd(&g_cursor[dp[r]], 1);
            g_srcc[p] = sp[r];
            g_dot1[p] = d1;
            g_dot2[p] = d2;
            float4* o = &g_ea[(size_t)p * 4];
            o[0] = A; o[1] = B; o[2] = C; o[3] = Dd;
        }
    }
}

// ---------------- feature transform: h = x@W, hs = h.a_s, hd = h.a_d --------
__global__ void __launch_bounds__(256) k_feat(const float* __restrict__ xin,
                                              const float* __restrict__ W,
                                              const float* __restrict__ a_s,
                                              const float* __restrict__ a_d,
                                              int use_c1) {
    __shared__ u64 sW2[D * 32];
    __shared__ float sx[8][4][D];
    __shared__ u64 sas2[32], sad2[32];
    const float* __restrict__ x = use_c1 ? (const float*)g_c1 : xin;
    int tid = threadIdx.x;
    for (int i = tid; i < D * 32; i += 256) sW2[i] = ((const u64*)W)[i];
    if (tid < 32) { sas2[tid] = ((const u64*)a_s)[tid]; sad2[tid] = ((const u64*)a_d)[tid]; }
    __syncthreads();
    int warp = tid >> 5, lane = tid & 31;
    F2U asv; asv.u = sas2[lane];
    F2U adv; adv.u = sad2[lane];
    int gw = blockIdx.x * 8 + warp;
    int nw = gridDim.x * 8;
    for (int r0 = gw * 4; r0 < NN; r0 += nw * 4) {
        #pragma unroll
        for (int r = 0; r < 4; r++) {
            int row = r0 + r;
            sx[warp][r][lane]      = x[row * D + lane];
            sx[warp][r][lane + 32] = x[row * D + lane + 32];
        }
        __syncwarp();
        F2U acc[4];
        #pragma unroll
        for (int r = 0; r < 4; r++) acc[r].u = 0ull;
        #pragma unroll
        for (int k = 0; k < D; k++) {
            u64 wp = sW2[k * 32 + lane];
            #pragma unroll
            for (int r = 0; r < 4; r++) {
                float xv = sx[warp][r][k];
                acc[r].u = fma2(pack2(xv, xv), wp, acc[r].u);
            }
        }
        #pragma unroll
        for (int r = 0; r < 4; r++) {
            int row = r0 + r;
            g_h[row * 32 + lane] = acc[r].f;
            float ps = acc[r].f.x * asv.f.x + acc[r].f.y * asv.f.y;
            float pd = acc[r].f.x * adv.f.x + acc[r].f.y * adv.f.y;
            #pragma unroll
            for (int o = 16; o; o >>= 1) {
                ps += __shfl_xor_sync(0xffffffffu, ps, o);
                pd += __shfl_xor_sync(0xffffffffu, pd, o);
            }
            if (lane == 0) { g_hs[row] = ps; g_hd[row] = pd; }
        }
        __syncwarp();
    }
}

// ---------------- fused GAT (3-pass, R2 structure): warp per dst node -------
// lane owns dim pair (2l, 2l+1); We resident in registers
__global__ void __launch_bounds__(256, 3) k_gat(const float* __restrict__ We,
                                                const float* __restrict__ bias,
                                                float* __restrict__ dout,
                                                int layer2) {
    __shared__ u64 sb2[32];
    float* __restrict__ out = layer2 ? dout : (float*)g_c1;
    const float* __restrict__ dot = layer2 ? g_dot2 : g_dot1;
    int tid = threadIdx.x, lane = tid & 31, warp = tid >> 5;
    if (tid < 32) sb2[tid] = ((const u64*)bias)[tid];
    __syncthreads();

    // register-resident We k-pairs for this lane's two dims
    int d0 = 2 * lane, d1 = d0 + 1;
    u64 wd0[8], wd1[8];
    #pragma unroll
    for (int j = 0; j < 8; j++) {
        wd0[j] = pack2(We[(2 * j) * D + d0], We[(2 * j + 1) * D + d0]);
        wd1[j] = pack2(We[(2 * j) * D + d1], We[(2 * j + 1) * D + d1]);
    }
    F2U bv; bv.u = sb2[lane];

    int gw = blockIdx.x * 8 + warp;
    int nw = gridDim.x * 8;

    for (int n = gw; n < NN; n += nw) {
        int beg = g_rowptr[n], end = g_rowptr[n + 1];
        float o0, o1;
        if (beg == end) {
            o0 = 0.f; o1 = 0.f;
        } else {
            float hdn = g_hd[n];
            // ---- pass 1: logits (recomputable) + segment max, lane-parallel --
            float mmax = -CUDART_INF_F;
            for (int idx = beg + lane; idx < end; idx += 32) {
                int sr = g_srcc[idx];
                float l = g_hs[sr] + hdn + dot[idx];
                l = fmaxf(l, ATT_SLOPE * l);            // leaky_relu(l, 0.2)
                mmax = fmaxf(mmax, l);
            }
            #pragma unroll
            for (int o = 16; o; o >>= 1)
                mmax = fmaxf(mmax, __shfl_xor_sync(0xffffffffu, mmax, o));

            // ---- pass 1b: recompute l, p = exp(l - m), store p, sum ---------
            float s = 0.f;
            for (int idx = beg + lane; idx < end; idx += 32) {
                int sr = g_srcc[idx];
                float l = g_hs[sr] + hdn + dot[idx];
                l = fmaxf(l, ATT_SLOPE * l);
                float p = __expf(l - mmax);             // arg <= 0
                g_l[idx] = p;
                s += p;
            }
            #pragma unroll
            for (int o = 16; o; o >>= 1)
                s += __shfl_xor_sync(0xffffffffu, s, o);
            __threadfence_block();
            __syncwarp();
            float inv = 1.0f / s;                       // s >= 1 always

            // ---- pass 2: max over edges of p*(h[src]+e), dims in lanes ------
            float a0 = -CUDART_INF_F, a1 = -CUDART_INF_F;
            for (int idx = beg; idx < end; idx++) {
                int sr  = g_srcc[idx];
                float p = g_l[idx];
                F2U hu; hu.f = g_h[sr * 32 + lane];
                const float4* ea4 = &g_ea[(size_t)idx * 4];
                float4 A = ea4[0], B = ea4[1], C = ea4[2], Dd = ea4[3];
                u64 p0 = pack2(A.x,  A.y);
                u64 p1 = pack2(A.z,  A.w);
                u64 p2 = pack2(B.x,  B.y);
                u64 p3 = pack2(B.z,  B.w);
                u64 p4 = pack2(C.x,  C.y);
                u64 p5 = pack2(C.z,  C.w);
                u64 p6 = pack2(Dd.x, Dd.y);
                u64 p7 = pack2(Dd.z, Dd.w);
                u64 e0 = 0ull, e1 = 0ull;
                e0 = fma2(p0, wd0[0], e0);  e1 = fma2(p0, wd1[0], e1);
                e0 = fma2(p1, wd0[1], e0);  e1 = fma2(p1, wd1[1], e1);
                e0 = fma2(p2, wd0[2], e0);  e1 = fma2(p2, wd1[2], e1);
                e0 = fma2(p3, wd0[3], e0);  e1 = fma2(p3, wd1[3], e1);
                e0 = fma2(p4, wd0[4], e0);  e1 = fma2(p4, wd1[4], e1);
                e0 = fma2(p5, wd0[5], e0);  e1 = fma2(p5, wd1[5], e1);
                e0 = fma2(p6, wd0[6], e0);  e1 = fma2(p6, wd1[6], e1);
                e0 = fma2(p7, wd0[7], e0);  e1 = fma2(p7, wd1[7], e1);
                F2U E0; E0.u = e0;
                F2U E1; E1.u = e1;
                float v0 = hu.f.x + (E0.f.x + E0.f.y);
                float v1 = hu.f.y + (E1.f.x + E1.f.y);
                a0 = fmaxf(a0, p * v0);
                a1 = fmaxf(a1, p * v1);
            }
            o0 = a0 * inv;
            o1 = a1 * inv;
        }
        o0 += bv.f.x;
        o1 += bv.f.y;
        o0 = fmaxf(o0, ACT_SLOPE * o0);                 // leaky_relu(., 0.01)
        o1 = fmaxf(o1, ACT_SLOPE * o1);
        ((float2*)out)[n * 32 + lane] = make_float2(o0, o1);
    }
}

// ---------------- launch -----------------------------------------------------
extern "C" void kernel_launch(void* const* d_in, const int* in_sizes, int n_in,
                              void* d_out, int out_size) {
    const float* X     = (const float*)d_in[0];
    const int*   ei    = (const int*)  d_in[1];
    const float* eattr = (const float*)d_in[2];
    const float* W1  = (const float*)d_in[3];
    const float* We1 = (const float*)d_in[4];
    const float* as1 = (const float*)d_in[5];
    const float* ad1 = (const float*)d_in[6];
    const float* ae1 = (const float*)d_in[7];
    const float* b1  = (const float*)d_in[8];
    const float* W2  = (const float*)d_in[9];
    const float* We2 = (const float*)d_in[10];
    const float* as2 = (const float*)d_in[11];
    const float* ad2 = (const float*)d_in[12];
    const float* ae2 = (const float*)d_in[13];
    const float* b2  = (const float*)d_in[14];

    const int* srcp = ei;
    const int* dstp = ei + EE;
    float* out = (float*)d_out;

    const int E4B = (EE / 4 + 255) / 256;        // 1563
    const int NB  = (NN + 255) / 256;            // 196
    const int SB  = (NN + 1023) / 1024;          // 49
    const int FB  = 296;
    const int GB  = 444;

    // CSR build + edge preprocessing (once per launch, shared by both layers)
    k_prep<<<1, 32>>>(We1, ae1, We2, ae2);
    k_zero_deg<<<NB, 256>>>();
    k_hist<<<E4B, 256>>>(dstp);
    k_scan1<<<SB, 1024>>>();
    k_scan2<<<NB, 256>>>();
    k_scatter<<<E4B, 256>>>(srcp, dstp, eattr);

    // layer 1
    k_feat<<<FB, 256>>>(X, W1, as1, ad1, /*use_c1=*/0);
    k_gat <<<GB, 256>>>(We1, b1, out, /*layer2=*/0);

    // layer 2
    k_feat<<<FB, 256>>>(nullptr, W2, as2, ad2, /*use_c1=*/1);
    k_gat <<<GB, 256>>>(We2, b2, out, /*layer2=*/1);
}

// round 5
// speedup vs baseline: 1.3069x; 1.0151x over previous
#include <cuda_runtime.h>
#include <math_constants.h>

#define NN   50000
#define EE   1600000
#define D    64
#define DE   16
#define ATT_SLOPE 0.2f
#define ACT_SLOPE 0.01f

typedef unsigned long long u64;
union F2U { u64 u; float2 f; };

__device__ __forceinline__ u64 fma2(u64 a, u64 b, u64 c) {
    u64 d; asm("fma.rn.f32x2 %0, %1, %2, %3;" : "=l"(d) : "l"(a), "l"(b), "l"(c));
    return d;
}
__device__ __forceinline__ u64 pack2(float x, float y) {
    F2U t; t.f = make_float2(x, y); return t.u;
}

// ---------------- scratch (device globals; no allocation allowed) -----------
__device__ float2 g_h [NN * 32];   // transformed features, dim pairs (2l,2l+1)
__device__ float2 g_c1[NN * 32];   // layer-1 output
__device__ float  g_hs[NN];
__device__ float  g_hd[NN];
__device__ float  g_l [EE];        // logits, then p, CSR order
__device__ float  g_dot1[EE];      // edge_attr @ (We1@ae1), CSR order
__device__ float  g_dot2[EE];      // edge_attr @ (We2@ae2), CSR order
__device__ int    g_deg[NN];
__device__ int    g_rowptr[NN + 1];
__device__ int    g_cursor[NN];
__device__ int    g_eid [EE];      // CSR -> original edge id
__device__ int    g_srcc[EE];      // CSR-ordered src node
__device__ int    g_bsum[64];
__device__ float  g_wea1[DE], g_wea2[DE];

// ---------------- tiny prep: wea = We @ ae for both layers -------------------
__global__ void k_prep(const float* __restrict__ We1, const float* __restrict__ ae1,
                       const float* __restrict__ We2, const float* __restrict__ ae2) {
    int t = threadIdx.x;
    if (t < DE) {
        float a = 0.f;
        #pragma unroll
        for (int d = 0; d < D; d++) a = fmaf(We1[t * D + d], ae1[d], a);
        g_wea1[t] = a;
    } else {
        int j = t - DE;
        float a = 0.f;
        #pragma unroll
        for (int d = 0; d < D; d++) a = fmaf(We2[j * D + d], ae2[d], a);
        g_wea2[j] = a;
    }
}

// ---------------- CSR construction ------------------------------------------
__global__ void k_zero_deg() {
    int i = blockIdx.x * blockDim.x + threadIdx.x;
    if (i < NN) g_deg[i] = 0;
}

__global__ void k_hist(const int* __restrict__ dst) {
    int i = blockIdx.x * blockDim.x + threadIdx.x;
    if (i < EE / 4) {
        int4 v = ((const int4*)dst)[i];
        atomicAdd(&g_deg[v.x], 1);
        atomicAdd(&g_deg[v.y], 1);
        atomicAdd(&g_deg[v.z], 1);
        atomicAdd(&g_deg[v.w], 1);
    }
}

__global__ void k_scan1() {
    __shared__ int wsum[32];
    int tid = threadIdx.x, lane = tid & 31, wid = tid >> 5;
    int i = blockIdx.x * 1024 + tid;
    int v = (i < NN) ? g_deg[i] : 0;
    int x = v;
    #pragma unroll
    for (int o = 1; o < 32; o <<= 1) {
        int t = __shfl_up_sync(0xffffffffu, x, o);
        if (lane >= o) x += t;
    }
    if (lane == 31) wsum[wid] = x;
    __syncthreads();
    if (wid == 0) {
        int w = wsum[lane];
        #pragma unroll
        for (int o = 1; o < 32; o <<= 1) {
            int t = __shfl_up_sync(0xffffffffu, w, o);
            if (lane >= o) w += t;
        }
        wsum[lane] = w;
    }
    __syncthreads();
    int off = wid ? wsum[wid - 1] : 0;
    if (i < NN) g_rowptr[i] = x - v + off;
    if (tid == 1023) g_bsum[blockIdx.x] = x + off;
}

__global__ void k_scan2() {
    int i = blockIdx.x * blockDim.x + threadIdx.x;
    if (i == 0) g_rowptr[NN] = EE;
    if (i < NN) {
        int b = i >> 10;
        int off = 0;
        for (int j = 0; j < b; j++) off += g_bsum[j];
        int r = g_rowptr[i] + off;
        g_rowptr[i] = r;
        g_cursor[i] = r;
    }
}

// scatter: CSR eid/src lists + per-edge attention dot scalars (both layers)
__global__ void k_scatter(const int* __restrict__ src, const int* __restrict__ dst,
                          const float* __restrict__ eattr) {
    __shared__ float sw1[DE], sw2[DE];
    if (threadIdx.x < DE) sw1[threadIdx.x] = g_wea1[threadIdx.x];
    else if (threadIdx.x < 2 * DE) sw2[threadIdx.x - DE] = g_wea2[threadIdx.x - DE];
    __syncthreads();
    int i = blockIdx.x * blockDim.x + threadIdx.x;
    if (i < EE / 4) {
        int4 dv = ((const int4*)dst)[i];
        int4 sv = ((const int4*)src)[i];
        const int* dp = &dv.x;
        const int* sp = &sv.x;
        #pragma unroll
        for (int r = 0; r < 4; r++) {
            int e = 4 * i + r;
            const float4* ea4 = (const float4*)(eattr + (size_t)e * DE);
            float4 A = ea4[0], B = ea4[1], C = ea4[2], Dd = ea4[3];
            float d1 = 0.f, d2 = 0.f;
            #pragma unroll
            for (int k = 0; k < 4; k++) { d1 = fmaf((&A.x)[k],  sw1[k],      d1); d2 = fmaf((&A.x)[k],  sw2[k],      d2); }
            #pragma unroll
            for (int k = 0; k < 4; k++) { d1 = fmaf((&B.x)[k],  sw1[k + 4],  d1); d2 = fmaf((&B.x)[k],  sw2[k + 4],  d2); }
            #pragma unroll
            for (int k = 0; k < 4; k++) { d1 = fmaf((&C.x)[k],  sw1[k + 8],  d1); d2 = fmaf((&C.x)[k],  sw2[k + 8],  d2); }
            #pragma unroll
            for (int k = 0; k < 4; k++) { d1 = fmaf((&Dd.x)[k], sw1[k + 12], d1); d2 = fmaf((&Dd.x)[k], sw2[k + 12], d2); }
            int p = atomicAdd(&g_cursor[dp[r]], 1);
            g_eid[p]  = e;
            g_srcc[p] = sp[r];
            g_dot1[p] = d1;
            g_dot2[p] = d2;
        }
    }
}

// ---------------- feature transform: h = x@W, hs = h.a_s, hd = h.a_d --------
__global__ void __launch_bounds__(256) k_feat(const float* __restrict__ xin,
                                              const float* __restrict__ W,
                                              const float* __restrict__ a_s,
                                              const float* __restrict__ a_d,
                                              int use_c1) {
    __shared__ u64 sW2[D * 32];
    __shared__ float sx[8][4][D];
    __shared__ u64 sas2[32], sad2[32];
    const float* __restrict__ x = use_c1 ? (const float*)g_c1 : xin;
    int tid = threadIdx.x;
    for (int i = tid; i < D * 32; i += 256) sW2[i] = ((const u64*)W)[i];
    if (tid < 32) { sas2[tid] = ((const u64*)a_s)[tid]; sad2[tid] = ((const u64*)a_d)[tid]; }
    __syncthreads();
    int warp = tid >> 5, lane = tid & 31;
    F2U asv; asv.u = sas2[lane];
    F2U adv; adv.u = sad2[lane];
    int gw = blockIdx.x * 8 + warp;
    int nw = gridDim.x * 8;
    for (int r0 = gw * 4; r0 < NN; r0 += nw * 4) {
        #pragma unroll
        for (int r = 0; r < 4; r++) {
            int row = r0 + r;
            sx[warp][r][lane]      = x[row * D + lane];
            sx[warp][r][lane + 32] = x[row * D + lane + 32];
        }
        __syncwarp();
        F2U acc[4];
        #pragma unroll
        for (int r = 0; r < 4; r++) acc[r].u = 0ull;
        #pragma unroll
        for (int k = 0; k < D; k++) {
            u64 wp = sW2[k * 32 + lane];
            #pragma unroll
            for (int r = 0; r < 4; r++) {
                float xv = sx[warp][r][k];
                acc[r].u = fma2(pack2(xv, xv), wp, acc[r].u);
            }
        }
        #pragma unroll
        for (int r = 0; r < 4; r++) {
            int row = r0 + r;
            g_h[row * 32 + lane] = acc[r].f;
            float ps = acc[r].f.x * asv.f.x + acc[r].f.y * asv.f.y;
            float pd = acc[r].f.x * adv.f.x + acc[r].f.y * adv.f.y;
            #pragma unroll
            for (int o = 16; o; o >>= 1) {
                ps += __shfl_xor_sync(0xffffffffu, ps, o);
                pd += __shfl_xor_sync(0xffffffffu, pd, o);
            }
            if (lane == 0) { g_hs[row] = ps; g_hd[row] = pd; }
        }
        __syncwarp();
    }
}

// ---------------- fused GAT (3-pass): warp per dst node ----------------------
// lane owns dim pair (2l, 2l+1); We resident in registers
__global__ void __launch_bounds__(256, 3) k_gat(const float* __restrict__ edge_attr,
                                                const float* __restrict__ We,
                                                const float* __restrict__ bias,
                                                float* __restrict__ dout,
                                                int layer2) {
    __shared__ u64 sb2[32];
    float* __restrict__ out = layer2 ? dout : (float*)g_c1;
    const float* __restrict__ dot = layer2 ? g_dot2 : g_dot1;
    int tid = threadIdx.x, lane = tid & 31, warp = tid >> 5;
    if (tid < 32) sb2[tid] = ((const u64*)bias)[tid];
    __syncthreads();

    // register-resident We k-pairs for this lane's two dims
    int d0 = 2 * lane, d1 = d0 + 1;
    u64 wd0[8], wd1[8];
    #pragma unroll
    for (int j = 0; j < 8; j++) {
        wd0[j] = pack2(We[(2 * j) * D + d0], We[(2 * j + 1) * D + d0]);
        wd1[j] = pack2(We[(2 * j) * D + d1], We[(2 * j + 1) * D + d1]);
    }
    F2U bv; bv.u = sb2[lane];

    int gw = blockIdx.x * 8 + warp;
    int nw = gridDim.x * 8;

    for (int n = gw; n < NN; n += nw) {
        int beg = g_rowptr[n], end = g_rowptr[n + 1];
        float o0, o1;
        if (beg == end) {
            o0 = 0.f; o1 = 0.f;
        } else {
            float hdn = g_hd[n];
            // ---- pass 1: logits from precomputed dots + segment max ---------
            float mmax = -CUDART_INF_F;
            for (int idx = beg + lane; idx < end; idx += 32) {
                int sr = g_srcc[idx];
                float l = g_hs[sr] + hdn + dot[idx];
                l = fmaxf(l, ATT_SLOPE * l);            // leaky_relu(l, 0.2)
                g_l[idx] = l;
                mmax = fmaxf(mmax, l);
            }
            #pragma unroll
            for (int o = 16; o; o >>= 1)
                mmax = fmaxf(mmax, __shfl_xor_sync(0xffffffffu, mmax, o));
            __syncwarp();

            // ---- pass 1b: p = exp(l - m), store p, sum ----------------------
            float s = 0.f;
            for (int idx = beg + lane; idx < end; idx += 32) {
                float p = __expf(g_l[idx] - mmax);      // arg <= 0
                g_l[idx] = p;
                s += p;
            }
            #pragma unroll
            for (int o = 16; o; o >>= 1)
                s += __shfl_xor_sync(0xffffffffu, s, o);
            __threadfence_block();
            __syncwarp();
            float inv = 1.0f / s;                       // s >= 1 always

            // ---- pass 2: max over edges of p*(h[src]+e), dims in lanes ------
            float a0 = -CUDART_INF_F, a1 = -CUDART_INF_F;
            for (int idx = beg; idx < end; idx++) {
                int e   = g_eid[idx];
                int sr  = g_srcc[idx];
                float p = g_l[idx];
                F2U hu; hu.f = g_h[sr * 32 + lane];
                const float4* ea4 = (const float4*)(edge_attr + (size_t)e * DE);
                float4 A = ea4[0], B = ea4[1], C = ea4[2], Dd = ea4[3];
                u64 p0 = pack2(A.x,  A.y);
                u64 p1 = pack2(A.z,  A.w);
                u64 p2 = pack2(B.x,  B.y);
                u64 p3 = pack2(B.z,  B.w);
                u64 p4 = pack2(C.x,  C.y);
                u64 p5 = pack2(C.z,  C.w);
                u64 p6 = pack2(Dd.x, Dd.y);
                u64 p7 = pack2(Dd.z, Dd.w);
                u64 e0 = 0ull, e1 = 0ull;
                e0 = fma2(p0, wd0[0], e0);  e1 = fma2(p0, wd1[0], e1);
                e0 = fma2(p1, wd0[1], e0);  e1 = fma2(p1, wd1[1], e1);
                e0 = fma2(p2, wd0[2], e0);  e1 = fma2(p2, wd1[2], e1);
                e0 = fma2(p3, wd0[3], e0);  e1 = fma2(p3, wd1[3], e1);
                e0 = fma2(p4, wd0[4], e0);  e1 = fma2(p4, wd1[4], e1);
                e0 = fma2(p5, wd0[5], e0);  e1 = fma2(p5, wd1[5], e1);
                e0 = fma2(p6, wd0[6], e0);  e1 = fma2(p6, wd1[6], e1);
                e0 = fma2(p7, wd0[7], e0);  e1 = fma2(p7, wd1[7], e1);
                F2U E0; E0.u = e0;
                F2U E1; E1.u = e1;
                float v0 = hu.f.x + (E0.f.x + E0.f.y);
                float v1 = hu.f.y + (E1.f.x + E1.f.y);
                a0 = fmaxf(a0, p * v0);
                a1 = fmaxf(a1, p * v1);
            }
            o0 = a0 * inv;
            o1 = a1 * inv;
        }
        o0 += bv.f.x;
        o1 += bv.f.y;
        o0 = fmaxf(o0, ACT_SLOPE * o0);                 // leaky_relu(., 0.01)
        o1 = fmaxf(o1, ACT_SLOPE * o1);
        ((float2*)out)[n * 32 + lane] = make_float2(o0, o1);
    }
}

// ---------------- launch -----------------------------------------------------
extern "C" void kernel_launch(void* const* d_in, const int* in_sizes, int n_in,
                              void* d_out, int out_size) {
    const float* X     = (const float*)d_in[0];
    const int*   ei    = (const int*)  d_in[1];
    const float* eattr = (const float*)d_in[2];
    const float* W1  = (const float*)d_in[3];
    const float* We1 = (const float*)d_in[4];
    const float* as1 = (const float*)d_in[5];
    const float* ad1 = (const float*)d_in[6];
    const float* ae1 = (const float*)d_in[7];
    const float* b1  = (const float*)d_in[8];
    const float* W2  = (const float*)d_in[9];
    const float* We2 = (const float*)d_in[10];
    const float* as2 = (const float*)d_in[11];
    const float* ad2 = (const float*)d_in[12];
    const float* ae2 = (const float*)d_in[13];
    const float* b2  = (const float*)d_in[14];

    const int* srcp = ei;
    const int* dstp = ei + EE;
    float* out = (float*)d_out;

    const int E4B = (EE / 4 + 255) / 256;        // 1563
    const int NB  = (NN + 255) / 256;            // 196
    const int SB  = (NN + 1023) / 1024;          // 49
    const int FB  = 296;
    const int GB  = 444;

    // CSR build + per-edge dot precompute (once per launch, both layers)
    k_prep<<<1, 32>>>(We1, ae1, We2, ae2);
    k_zero_deg<<<NB, 256>>>();
    k_hist<<<E4B, 256>>>(dstp);
    k_scan1<<<SB, 1024>>>();
    k_scan2<<<NB, 256>>>();
    k_scatter<<<E4B, 256>>>(srcp, dstp, eattr);

    // layer 1
    k_feat<<<FB, 256>>>(X, W1, as1, ad1, /*use_c1=*/0);
    k_gat <<<GB, 256>>>(eattr, We1, b1, out, /*layer2=*/0);

    // layer 2
    k_feat<<<FB, 256>>>(nullptr, W2, as2, ad2, /*use_c1=*/1);
    k_gat <<<GB, 256>>>(eattr, We2, b2, out, /*layer2=*/1);
}

// round 6
// speedup vs baseline: 1.7645x; 1.3502x over previous
#include <cuda_runtime.h>
#include <math_constants.h>

#define NN   50000
#define EE   1600000
#define D    64
#define DE   16
#define ATT_SLOPE 0.2f
#define ACT_SLOPE 0.01f

typedef unsigned long long u64;
union F2U { u64 u; float2 f; };

__device__ __forceinline__ u64 fma2(u64 a, u64 b, u64 c) {
    u64 d; asm("fma.rn.f32x2 %0, %1, %2, %3;" : "=l"(d) : "l"(a), "l"(b), "l"(c));
    return d;
}
__device__ __forceinline__ u64 pack2(float x, float y) {
    F2U t; t.f = make_float2(x, y); return t.u;
}

// ---------------- scratch (device globals; no allocation allowed) -----------
__device__ float2 g_h [NN * 32];   // transformed features, dim pairs (2l,2l+1)
__device__ float2 g_c1[NN * 32];   // layer-1 output
__device__ float  g_hs[NN];
__device__ float  g_hd[NN];
__device__ float  g_dot1[EE];      // edge_attr @ (We1@ae1), CSR order
__device__ float  g_dot2[EE];      // edge_attr @ (We2@ae2), CSR order
__device__ int    g_deg[NN];
__device__ int    g_rowptr[NN + 1];
__device__ int    g_cursor[NN];
__device__ int    g_eid [EE];      // CSR -> original edge id
__device__ int    g_srcc[EE];      // CSR-ordered src node
__device__ int    g_bsum[64];
__device__ float  g_wea1[DE], g_wea2[DE];

// ---------------- tiny prep: wea = We @ ae for both layers -------------------
__global__ void k_prep(const float* __restrict__ We1, const float* __restrict__ ae1,
                       const float* __restrict__ We2, const float* __restrict__ ae2) {
    int t = threadIdx.x;
    if (t < DE) {
        float a = 0.f;
        #pragma unroll
        for (int d = 0; d < D; d++) a = fmaf(We1[t * D + d], ae1[d], a);
        g_wea1[t] = a;
    } else {
        int j = t - DE;
        float a = 0.f;
        #pragma unroll
        for (int d = 0; d < D; d++) a = fmaf(We2[j * D + d], ae2[d], a);
        g_wea2[j] = a;
    }
}

// ---------------- CSR construction ------------------------------------------
__global__ void k_zero_deg() {
    int i = blockIdx.x * blockDim.x + threadIdx.x;
    if (i < NN) g_deg[i] = 0;
}

__global__ void k_hist(const int* __restrict__ dst) {
    int i = blockIdx.x * blockDim.x + threadIdx.x;
    if (i < EE / 4) {
        int4 v = ((const int4*)dst)[i];
        atomicAdd(&g_deg[v.x], 1);
        atomicAdd(&g_deg[v.y], 1);
        atomicAdd(&g_deg[v.z], 1);
        atomicAdd(&g_deg[v.w], 1);
    }
}

__global__ void k_scan1() {
    __shared__ int wsum[32];
    int tid = threadIdx.x, lane = tid & 31, wid = tid >> 5;
    int i = blockIdx.x * 1024 + tid;
    int v = (i < NN) ? g_deg[i] : 0;
    int x = v;
    #pragma unroll
    for (int o = 1; o < 32; o <<= 1) {
        int t = __shfl_up_sync(0xffffffffu, x, o);
        if (lane >= o) x += t;
    }
    if (lane == 31) wsum[wid] = x;
    __syncthreads();
    if (wid == 0) {
        int w = wsum[lane];
        #pragma unroll
        for (int o = 1; o < 32; o <<= 1) {
            int t = __shfl_up_sync(0xffffffffu, w, o);
            if (lane >= o) w += t;
        }
        wsum[lane] = w;
    }
    __syncthreads();
    int off = wid ? wsum[wid - 1] : 0;
    if (i < NN) g_rowptr[i] = x - v + off;
    if (tid == 1023) g_bsum[blockIdx.x] = x + off;
}

__global__ void k_scan2() {
    int i = blockIdx.x * blockDim.x + threadIdx.x;
    if (i == 0) g_rowptr[NN] = EE;
    if (i < NN) {
        int b = i >> 10;
        int off = 0;
        for (int j = 0; j < b; j++) off += g_bsum[j];
        int r = g_rowptr[i] + off;
        g_rowptr[i] = r;
        g_cursor[i] = r;
    }
}

// scatter: CSR eid/src lists + per-edge attention dot scalars (both layers)
__global__ void k_scatter(const int* __restrict__ src, const int* __restrict__ dst,
                          const float* __restrict__ eattr) {
    __shared__ float sw1[DE], sw2[DE];
    if (threadIdx.x < DE) sw1[threadIdx.x] = g_wea1[threadIdx.x];
    else if (threadIdx.x < 2 * DE) sw2[threadIdx.x - DE] = g_wea2[threadIdx.x - DE];
    __syncthreads();
    int i = blockIdx.x * blockDim.x + threadIdx.x;
    if (i < EE / 4) {
        int4 dv = ((const int4*)dst)[i];
        int4 sv = ((const int4*)src)[i];
        const int* dp = &dv.x;
        const int* sp = &sv.x;
        #pragma unroll
        for (int r = 0; r < 4; r++) {
            int e = 4 * i + r;
            const float4* ea4 = (const float4*)(eattr + (size_t)e * DE);
            float4 A = ea4[0], B = ea4[1], C = ea4[2], Dd = ea4[3];
            float d1 = 0.f, d2 = 0.f;
            #pragma unroll
            for (int k = 0; k < 4; k++) { d1 = fmaf((&A.x)[k],  sw1[k],      d1); d2 = fmaf((&A.x)[k],  sw2[k],      d2); }
            #pragma unroll
            for (int k = 0; k < 4; k++) { d1 = fmaf((&B.x)[k],  sw1[k + 4],  d1); d2 = fmaf((&B.x)[k],  sw2[k + 4],  d2); }
            #pragma unroll
            for (int k = 0; k < 4; k++) { d1 = fmaf((&C.x)[k],  sw1[k + 8],  d1); d2 = fmaf((&C.x)[k],  sw2[k + 8],  d2); }
            #pragma unroll
            for (int k = 0; k < 4; k++) { d1 = fmaf((&Dd.x)[k], sw1[k + 12], d1); d2 = fmaf((&Dd.x)[k], sw2[k + 12], d2); }
            int p = atomicAdd(&g_cursor[dp[r]], 1);
            g_eid[p]  = e;
            g_srcc[p] = sp[r];
            g_dot1[p] = d1;
            g_dot2[p] = d2;
        }
    }
}

// ---------------- feature transform: h = x@W, hs = h.a_s, hd = h.a_d --------
__global__ void __launch_bounds__(256) k_feat(const float* __restrict__ xin,
                                              const float* __restrict__ W,
                                              const float* __restrict__ a_s,
                                              const float* __restrict__ a_d,
                                              int use_c1) {
    __shared__ u64 sW2[D * 32];
    __shared__ float sx[8][4][D];
    __shared__ u64 sas2[32], sad2[32];
    const float* __restrict__ x = use_c1 ? (const float*)g_c1 : xin;
    int tid = threadIdx.x;
    for (int i = tid; i < D * 32; i += 256) sW2[i] = ((const u64*)W)[i];
    if (tid < 32) { sas2[tid] = ((const u64*)a_s)[tid]; sad2[tid] = ((const u64*)a_d)[tid]; }
    __syncthreads();
    int warp = tid >> 5, lane = tid & 31;
    F2U asv; asv.u = sas2[lane];
    F2U adv; adv.u = sad2[lane];
    int gw = blockIdx.x * 8 + warp;
    int nw = gridDim.x * 8;
    for (int r0 = gw * 4; r0 < NN; r0 += nw * 4) {
        #pragma unroll
        for (int r = 0; r < 4; r++) {
            int row = r0 + r;
            sx[warp][r][lane]      = x[row * D + lane];
            sx[warp][r][lane + 32] = x[row * D + lane + 32];
        }
        __syncwarp();
        F2U acc[4];
        #pragma unroll
        for (int r = 0; r < 4; r++) acc[r].u = 0ull;
        #pragma unroll
        for (int k = 0; k < D; k++) {
            u64 wp = sW2[k * 32 + lane];
            #pragma unroll
            for (int r = 0; r < 4; r++) {
                float xv = sx[warp][r][k];
                acc[r].u = fma2(pack2(xv, xv), wp, acc[r].u);
            }
        }
        #pragma unroll
        for (int r = 0; r < 4; r++) {
            int row = r0 + r;
            g_h[row * 32 + lane] = acc[r].f;
            float ps = acc[r].f.x * asv.f.x + acc[r].f.y * asv.f.y;
            float pd = acc[r].f.x * adv.f.x + acc[r].f.y * adv.f.y;
            #pragma unroll
            for (int o = 16; o; o >>= 1) {
                ps += __shfl_xor_sync(0xffffffffu, ps, o);
                pd += __shfl_xor_sync(0xffffffffu, pd, o);
            }
            if (lane == 0) { g_hs[row] = ps; g_hd[row] = pd; }
        }
        __syncwarp();
    }
}

// ---------------- fused GAT: chunked stage-then-aggregate --------------------
// warp per dst node; lane owns dim pair (2l,2l+1); We in registers.
// Per 32-edge chunk: lanes gather edge_attr in parallel into padded smem and
// compute p in registers; serial loop reads smem (broadcast) + shfl(p,src),
// with the h[src] row load double-buffered one edge ahead.
__global__ void __launch_bounds__(256, 3) k_gat(const float* __restrict__ edge_attr,
                                                const float* __restrict__ We,
                                                const float* __restrict__ bias,
                                                float* __restrict__ dout,
                                                int layer2) {
    __shared__ u64 sea[8][32][17];   // [warp][edge-in-chunk][8 pairs + pad]
    __shared__ u64 sb2[32];
    float* __restrict__ out = layer2 ? dout : (float*)g_c1;
    const float* __restrict__ dot = layer2 ? g_dot2 : g_dot1;
    int tid = threadIdx.x, lane = tid & 31, warp = tid >> 5;
    if (tid < 32) sb2[tid] = ((const u64*)bias)[tid];
    __syncthreads();

    // register-resident We k-pairs for this lane's two dims
    int d0 = 2 * lane, d1 = d0 + 1;
    u64 wd0[8], wd1[8];
    #pragma unroll
    for (int j = 0; j < 8; j++) {
        wd0[j] = pack2(We[(2 * j) * D + d0], We[(2 * j + 1) * D + d0]);
        wd1[j] = pack2(We[(2 * j) * D + d1], We[(2 * j + 1) * D + d1]);
    }
    F2U bv; bv.u = sb2[lane];

    int gw = blockIdx.x * 8 + warp;
    int nw = gridDim.x * 8;

    for (int n = gw; n < NN; n += nw) {
        int beg = g_rowptr[n], end = g_rowptr[n + 1];
        float o0, o1;
        if (beg == end) {
            o0 = 0.f; o1 = 0.f;
        } else {
            float hdn = g_hd[n];
            // ---- pass 1: segment max of logits (lane-parallel, cheap) -------
            float mmax = -CUDART_INF_F;
            for (int idx = beg + lane; idx < end; idx += 32) {
                float l = g_hs[g_srcc[idx]] + hdn + dot[idx];
                l = fmaxf(l, ATT_SLOPE * l);            // leaky_relu(l, 0.2)
                mmax = fmaxf(mmax, l);
            }
            #pragma unroll
            for (int o = 16; o; o >>= 1)
                mmax = fmaxf(mmax, __shfl_xor_sync(0xffffffffu, mmax, o));

            // ---- pass 2: chunked stage + aggregate --------------------------
            float s = 0.f;
            float a0 = -CUDART_INF_F, a1 = -CUDART_INF_F;
            for (int base = beg; base < end; base += 32) {
                int idx = base + lane;
                int cnt = min(32, end - base);
                int sr = 0; float p = 0.f;
                if (idx < end) {
                    sr = g_srcc[idx];
                    float l = g_hs[sr] + hdn + dot[idx];   // L1-hot (pass 1)
                    l = fmaxf(l, ATT_SLOPE * l);
                    p = __expf(l - mmax);                  // arg <= 0
                    s += p;
                    int e = g_eid[idx];
                    const float4* ea4 = (const float4*)(edge_attr + (size_t)e * DE);
                    float4 A = ea4[0], B = ea4[1], C = ea4[2], Dd = ea4[3];
                    u64* w8 = &sea[warp][lane][0];         // stride-17 pad: conflict-free
                    w8[0] = pack2(A.x,  A.y);
                    w8[1] = pack2(A.z,  A.w);
                    w8[2] = pack2(B.x,  B.y);
                    w8[3] = pack2(B.z,  B.w);
                    w8[4] = pack2(C.x,  C.y);
                    w8[5] = pack2(C.z,  C.w);
                    w8[6] = pack2(Dd.x, Dd.y);
                    w8[7] = pack2(Dd.z, Dd.w);
                }
                __syncwarp();
                // serial aggregation; h row double-buffered one edge ahead
                int sr0 = __shfl_sync(0xffffffffu, sr, 0);
                F2U hc; hc.f = g_h[sr0 * 32 + lane];
                for (int j = 0; j < cnt; j++) {
                    int jn = (j + 1 < cnt) ? (j + 1) : j;
                    int srn = __shfl_sync(0xffffffffu, sr, jn);
                    F2U hn; hn.f = g_h[srn * 32 + lane];
                    float pj = __shfl_sync(0xffffffffu, p, j);
                    const u64* row = &sea[warp][j][0];
                    u64 e0 = 0ull, e1 = 0ull;
                    #pragma unroll
                    for (int k = 0; k < 8; k++) {
                        u64 pk = row[k];                   // broadcast LDS.64
                        e0 = fma2(pk, wd0[k], e0);
                        e1 = fma2(pk, wd1[k], e1);
                    }
                    F2U E0; E0.u = e0;
                    F2U E1; E1.u = e1;
                    float v0 = hc.f.x + (E0.f.x + E0.f.y);
                    float v1 = hc.f.y + (E1.f.x + E1.f.y);
                    a0 = fmaxf(a0, pj * v0);
                    a1 = fmaxf(a1, pj * v1);
                    hc = hn;
                }
                __syncwarp();   // protect sea before next chunk overwrites
            }
            #pragma unroll
            for (int o = 16; o; o >>= 1)
                s += __shfl_xor_sync(0xffffffffu, s, o);
            float inv = 1.0f / s;                          // s >= 1 always
            o0 = a0 * inv;
            o1 = a1 * inv;
        }
        o0 += bv.f.x;
        o1 += bv.f.y;
        o0 = fmaxf(o0, ACT_SLOPE * o0);                    // leaky_relu(., 0.01)
        o1 = fmaxf(o1, ACT_SLOPE * o1);
        ((float2*)out)[n * 32 + lane] = make_float2(o0, o1);
    }
}

// ---------------- launch -----------------------------------------------------
extern "C" void kernel_launch(void* const* d_in, const int* in_sizes, int n_in,
                              void* d_out, int out_size) {
    const float* X     = (const float*)d_in[0];
    const int*   ei    = (const int*)  d_in[1];
    const float* eattr = (const float*)d_in[2];
    const float* W1  = (const float*)d_in[3];
    const float* We1 = (const float*)d_in[4];
    const float* as1 = (const float*)d_in[5];
    const float* ad1 = (const float*)d_in[6];
    const float* ae1 = (const float*)d_in[7];
    const float* b1  = (const float*)d_in[8];
    const float* W2  = (const float*)d_in[9];
    const float* We2 = (const float*)d_in[10];
    const float* as2 = (const float*)d_in[11];
    const float* ad2 = (const float*)d_in[12];
    const float* ae2 = (const float*)d_in[13];
    const float* b2  = (const float*)d_in[14];

    const int* srcp = ei;
    const int* dstp = ei + EE;
    float* out = (float*)d_out;

    const int E4B = (EE / 4 + 255) / 256;        // 1563
    const int NB  = (NN + 255) / 256;            // 196
    const int SB  = (NN + 1023) / 1024;          // 49
    const int FB  = 296;
    const int GB  = 444;

    // CSR build + per-edge dot precompute (once per launch, both layers)
    k_prep<<<1, 32>>>(We1, ae1, We2, ae2);
    k_zero_deg<<<NB, 256>>>();
    k_hist<<<E4B, 256>>>(dstp);
    k_scan1<<<SB, 1024>>>();
    k_scan2<<<NB, 256>>>();
    k_scatter<<<E4B, 256>>>(srcp, dstp, eattr);

    // layer 1
    k_feat<<<FB, 256>>>(X, W1, as1, ad1, /*use_c1=*/0);
    k_gat <<<GB, 256>>>(eattr, We1, b1, out, /*layer2=*/0);

    // layer 2
    k_feat<<<FB, 256>>>(nullptr, W2, as2, ad2, /*use_c1=*/1);
    k_gat <<<GB, 256>>>(eattr, We2, b2, out, /*layer2=*/1);
}